// round 2
// baseline (speedup 1.0000x reference)
#include <cuda_runtime.h>
#include <cstdint>

#define N_K   512
#define DIM    64
#define NTILE 256
#define RESULT_ELEMS 16777216   // 64*256*32*32

__device__ float g_h[N_K];   // 0.5 * ||e_k||^2

__global__ void compute_h_kernel(const float* __restrict__ w) {
    int k = threadIdx.x;
    if (k < N_K) {
        float s = 0.f;
        #pragma unroll
        for (int c = 0; c < DIM; ++c) {
            float v = w[c * N_K + k];
            s = fmaf(v, v, s);
        }
        g_h[k] = 0.5f * s;
    }
}

// 16B shared load as two 64-bit (f32x2) values
__device__ __forceinline__ void lds_v2u64(unsigned long long& a,
                                          unsigned long long& b,
                                          uint32_t addr) {
    asm volatile("ld.shared.v2.b64 {%0,%1}, [%2];"
                 : "=l"(a), "=l"(b) : "r"(addr));
}

// packed dual fp32 fma: d.lo += a.lo*b.lo ; d.hi += a.hi*b.hi
__device__ __forceinline__ void ffma2(unsigned long long& d,
                                      unsigned long long a,
                                      unsigned long long b) {
    asm volatile("fma.rn.f32x2 %0, %1, %2, %0;" : "+l"(d) : "l"(a), "l"(b));
}

__global__ __launch_bounds__(256, 2)
void vq_kernel(const float* __restrict__ x, const float* __restrict__ w,
               float* __restrict__ out) {
    extern __shared__ float smem[];
    float* xs2 = smem;                        // [DIM][128] duplicated x, 32 KB
    float* es  = smem + DIM * 128;            // [DIM][NTILE], 64 KB
    float* hs  = es + DIM * NTILE;            // [512], 2 KB
    int*   bks = (int*)(hs + N_K);            // [64]

    const int tid = threadIdx.x;
    const int bg  = blockIdx.x >> 4;
    const int mb  = blockIdx.x & 15;
    const int b   = bg >> 2;
    const int g   = bg & 3;
    const int hw0 = mb * 64;
    const int tx  = tid & 31;
    const int ty  = tid >> 5;

    // ---- load x tile duplicated: xs2[c][2m]=xs2[c][2m+1]=x[b,g*64+c,hw0+m] ----
    const float* xbase = x + (b * 256 + g * 64) * 1024 + hw0;
    {
        int m2 = tx * 2;           // even m
        int c0 = ty;               // 0..7
        #pragma unroll
        for (int i = 0; i < 8; ++i) {
            int c = c0 + i * 8;
            float2 v = *(const float2*)(xbase + c * 1024 + m2);
            *(float4*)(xs2 + c * 128 + 2 * m2) = make_float4(v.x, v.x, v.y, v.y);
        }
    }
    hs[tid]       = g_h[tid];
    hs[tid + 256] = g_h[tid + 256];

    const uint32_t s_xs2 = (uint32_t)__cvta_generic_to_shared(xs2) + ty * 64;  // 16 floats/warp
    const uint32_t s_es  = (uint32_t)__cvta_generic_to_shared(es) + tx * 16;

    float bestv[8];
    int   bestk[8];
    #pragma unroll
    for (int i = 0; i < 8; ++i) { bestv[i] = -3.4e38f; bestk[i] = 0; }

    for (int nc = 0; nc < 2; ++nc) {
        const int koff = nc * NTILE;
        __syncthreads();   // protect es from previous chunk's readers

        // ---- load e tile: es[c][n] = w[c][koff+n] (coalesced, vectorized) ----
        {
            int p  = tid & 63;
            int c0 = tid >> 6;
            #pragma unroll
            for (int i = 0; i < 16; ++i) {
                int c = c0 + i * 4;
                *(float4*)(es + c * NTILE + p * 4) =
                    *(const float4*)(w + c * N_K + koff + p * 4);
            }
        }
        __syncthreads();

        // ---- register-tiled GEMM, packed f32x2: 8 rows x 8 codes / thread ----
        unsigned long long acc[8][4];
        #pragma unroll
        for (int i = 0; i < 8; ++i)
            #pragma unroll
            for (int p = 0; p < 4; ++p) acc[i][p] = 0ULL;

        #pragma unroll 8
        for (int kk = 0; kk < DIM; ++kk) {
            unsigned long long av[8], ev[4];
            uint32_t xa = s_xs2 + kk * 512;    // 128 floats * 4B per row
            uint32_t ea = s_es  + kk * 1024;   // 256 floats * 4B per row
            lds_v2u64(av[0], av[1], xa);
            lds_v2u64(av[2], av[3], xa + 16);
            lds_v2u64(av[4], av[5], xa + 32);
            lds_v2u64(av[6], av[7], xa + 48);
            lds_v2u64(ev[0], ev[1], ea);           // codes tx*4 .. tx*4+3
            lds_v2u64(ev[2], ev[3], ea + 512);     // codes 128+tx*4 ..
            #pragma unroll
            for (int i = 0; i < 8; ++i)
                #pragma unroll
                for (int p = 0; p < 4; ++p)
                    ffma2(acc[i][p], av[i], ev[p]);
        }

        // ---- fused argmax epilogue: score = x.e - 0.5*||e||^2 ----
        #pragma unroll
        for (int p = 0; p < 4; ++p) {
            int n0 = (p < 2) ? (tx * 4 + p * 2) : (128 + tx * 4 + (p - 2) * 2);
            float h0 = hs[koff + n0];
            float h1 = hs[koff + n0 + 1];
            int   k0 = koff + n0;
            #pragma unroll
            for (int i = 0; i < 8; ++i) {
                float lo = __uint_as_float((unsigned)(acc[i][p] & 0xffffffffULL));
                float hi = __uint_as_float((unsigned)(acc[i][p] >> 32));
                float s0 = lo - h0;
                float s1 = hi - h1;
                if (s0 > bestv[i]) { bestv[i] = s0; bestk[i] = k0; }
                if (s1 > bestv[i]) { bestv[i] = s1; bestk[i] = k0 + 1; }
            }
        }
    }

    // ---- per-warp reduction over 32 lanes (codes); warp owns 8 m-rows ----
    #pragma unroll
    for (int i = 0; i < 8; ++i) {
        float v = bestv[i];
        int   k = bestk[i];
        #pragma unroll
        for (int off = 16; off > 0; off >>= 1) {
            float ov = __shfl_xor_sync(0xffffffffu, v, off);
            int   ok = __shfl_xor_sync(0xffffffffu, k, off);
            if (ov > v || (ov == v && ok < k)) { v = ov; k = ok; }
        }
        if (tx == 0) bks[ty * 8 + i] = k;
    }
    __syncthreads();

    // ---- write argmins (as float) ----
    if (tid < 64) {
        out[RESULT_ELEMS + (b * 4 + g) * 1024 + hw0 + tid] = (float)bks[tid];
    }

    // ---- write result: out[b, g*64+c, hw0+m] = w[c][k[m]] * 0.5 (coalesced) ----
    float* obase = out + (b * 256 + g * 64) * 1024 + hw0;
    {
        int m  = tid & 63;
        int c0 = tid >> 6;
        int k  = bks[m];
        #pragma unroll
        for (int i = 0; i < 16; ++i) {
            int c = c0 + i * 4;
            obase[c * 1024 + m] = w[c * N_K + k] * 0.5f;
        }
    }
}

extern "C" void kernel_launch(void* const* d_in, const int* in_sizes, int n_in,
                              void* d_out, int out_size) {
    const float* x = (const float*)d_in[0];   // (64, 256, 32, 32) fp32
    const float* w = (const float*)d_in[1];   // (64, 512) fp32
    float* out = (float*)d_out;               // result (16.7M) ++ argmins (262K)

    const int smem_bytes = (DIM * 128 + DIM * NTILE + N_K) * 4 + 64 * 4;
    cudaFuncSetAttribute(vq_kernel, cudaFuncAttributeMaxDynamicSharedMemorySize,
                         smem_bytes);

    compute_h_kernel<<<1, N_K>>>(w);
    vq_kernel<<<4096, 256, smem_bytes>>>(x, w, out);
}

// round 3
// speedup vs baseline: 1.0234x; 1.0234x over previous
#include <cuda_runtime.h>
#include <cstdint>

#define N_K   512
#define DIM    64
#define NTILE 128
#define RESULT_ELEMS 16777216   // 64*256*32*32

__device__ float g_h[N_K];   // 0.5 * ||e_k||^2

__global__ void compute_h_kernel(const float* __restrict__ w) {
    int k = threadIdx.x;
    if (k < N_K) {
        float s = 0.f;
        #pragma unroll
        for (int c = 0; c < DIM; ++c) {
            float v = w[c * N_K + k];
            s = fmaf(v, v, s);
        }
        g_h[k] = 0.5f * s;
    }
}

__global__ __launch_bounds__(256, 3)
void vq_kernel(const float* __restrict__ x, const float* __restrict__ w,
               float* __restrict__ out) {
    extern __shared__ float smem[];
    float* xs  = smem;                        // [DIM][64]   16 KB
    float* es  = smem + DIM * 64;             // [DIM][NTILE] 32 KB
    float* hs  = es + DIM * NTILE;            // [512]        2 KB
    int*   bks = (int*)(hs + N_K);            // [64]

    const int tid = threadIdx.x;
    const int bg  = blockIdx.x >> 4;
    const int mb  = blockIdx.x & 15;
    const int b   = bg >> 2;
    const int g   = bg & 3;
    const int hw0 = mb * 64;
    const int tx  = tid & 31;   // n lanes
    const int ty  = tid >> 5;   // m warps

    // ---- load x tile: xs[c][m] = x[b, g*64+c, hw0+m] (coalesced over m) ----
    const float* xbase = x + (b * 256 + g * 64) * 1024 + hw0;
    {
        int m  = tid & 63;
        int c0 = tid >> 6;
        #pragma unroll
        for (int i = 0; i < 16; ++i) {
            int c = c0 + i * 4;
            xs[c * 64 + m] = xbase[c * 1024 + m];
        }
    }
    hs[tid]       = g_h[tid];
    hs[tid + 256] = g_h[tid + 256];

    const uint32_t s_xs = (uint32_t)__cvta_generic_to_shared(xs) + ty * 32;
    const uint32_t s_es = (uint32_t)__cvta_generic_to_shared(es) + tx * 16;

    float bestv[8];
    int   bestk[8];
    #pragma unroll
    for (int i = 0; i < 8; ++i) { bestv[i] = -3.4e38f; bestk[i] = 0; }

    for (int nc = 0; nc < 4; ++nc) {
        const int koff = nc * NTILE;
        __syncthreads();   // previous chunk's es readers done

        // ---- load e tile: es[c][n] = w[c][koff+n] (float4, coalesced) ----
        {
            int p  = tid & 31;          // 32 float4 per 128-wide row
            int c0 = tid >> 5;          // 8 row groups
            #pragma unroll
            for (int i = 0; i < 8; ++i) {
                int c = c0 + i * 8;
                *(float4*)(es + c * NTILE + p * 4) =
                    *(const float4*)(w + c * N_K + koff + p * 4);
            }
        }
        __syncthreads();

        // ---- 8x4 register-tiled GEMM over the 64-dim reduction ----
        float acc[8][4];
        #pragma unroll
        for (int i = 0; i < 8; ++i)
            #pragma unroll
            for (int j = 0; j < 4; ++j) acc[i][j] = 0.f;

        #pragma unroll 8
        for (int kk = 0; kk < DIM; ++kk) {
            float4 a0 = *(const float4*)(xs + kk * 64 + ty * 8);      // broadcast
            float4 a1 = *(const float4*)(xs + kk * 64 + ty * 8 + 4);  // broadcast
            float4 e0;
            asm volatile("ld.shared.v4.f32 {%0,%1,%2,%3}, [%4];"
                         : "=f"(e0.x), "=f"(e0.y), "=f"(e0.z), "=f"(e0.w)
                         : "r"(s_es + (uint32_t)(kk * (NTILE * 4))));
            float av[8] = {a0.x, a0.y, a0.z, a0.w, a1.x, a1.y, a1.z, a1.w};
            float ev[4] = {e0.x, e0.y, e0.z, e0.w};
            #pragma unroll
            for (int i = 0; i < 8; ++i)
                #pragma unroll
                for (int j = 0; j < 4; ++j)
                    acc[i][j] = fmaf(av[i], ev[j], acc[i][j]);
        }

        // ---- fused argmax epilogue: score = x.e - 0.5*||e||^2 ----
        #pragma unroll
        for (int j = 0; j < 4; ++j) {
            int n = tx * 4 + j;
            float h = hs[koff + n];
            int   k = koff + n;
            #pragma unroll
            for (int i = 0; i < 8; ++i) {
                float s = acc[i][j] - h;
                if (s > bestv[i]) { bestv[i] = s; bestk[i] = k; }
            }
        }
    }

    // ---- per-warp reduction over 32 lanes (codes); warp owns 8 m-rows ----
    #pragma unroll
    for (int i = 0; i < 8; ++i) {
        float v = bestv[i];
        int   k = bestk[i];
        #pragma unroll
        for (int off = 16; off > 0; off >>= 1) {
            float ov = __shfl_xor_sync(0xffffffffu, v, off);
            int   ok = __shfl_xor_sync(0xffffffffu, k, off);
            if (ov > v || (ov == v && ok < k)) { v = ov; k = ok; }
        }
        if (tx == 0) bks[ty * 8 + i] = k;
    }
    __syncthreads();

    // ---- write argmins (as float) ----
    if (tid < 64) {
        out[RESULT_ELEMS + (b * 4 + g) * 1024 + hw0 + tid] = (float)bks[tid];
    }

    // ---- write result: out[b, g*64+c, hw0+m] = w[c][k[m]] * 0.5 (coalesced) ----
    float* obase = out + (b * 256 + g * 64) * 1024 + hw0;
    {
        int m  = tid & 63;
        int c0 = tid >> 6;
        int k  = bks[m];
        #pragma unroll
        for (int i = 0; i < 16; ++i) {
            int c = c0 + i * 4;
            obase[c * 1024 + m] = w[c * N_K + k] * 0.5f;
        }
    }
}

extern "C" void kernel_launch(void* const* d_in, const int* in_sizes, int n_in,
                              void* d_out, int out_size) {
    const float* x = (const float*)d_in[0];   // (64, 256, 32, 32) fp32
    const float* w = (const float*)d_in[1];   // (64, 512) fp32
    float* out = (float*)d_out;               // result (16.7M) ++ argmins (262K)

    const int smem_bytes = (DIM * 64 + DIM * NTILE + N_K) * 4 + 64 * 4;
    cudaFuncSetAttribute(vq_kernel, cudaFuncAttributeMaxDynamicSharedMemorySize,
                         smem_bytes);

    compute_h_kernel<<<1, N_K>>>(w);
    vq_kernel<<<4096, 256, smem_bytes>>>(x, w, out);
}

// round 6
// speedup vs baseline: 1.7388x; 1.6991x over previous
#include <cuda_runtime.h>
#include <cuda_fp16.h>
#include <cstdint>

#define RESULT_ELEMS 16777216   // 64*256*32*32

// smem layout (bytes)
#define OFF_EH    0        // E chunk hi [128][64] half, 16384  (aliases stage)
#define OFF_EL    16384    // E chunk lo, 16384                  (aliases stage)
#define OFF_XH    33792    // x hi [128][64] half, 16384
#define OFF_XL    50176    // x lo, 16384
#define OFF_H     66560    // 512 floats
#define OFF_BKS   68608    // 128 ints
#define SMEM_SZ   69120

__device__ float  g_h[512];        // 0.5*||e_k||^2 (exact fp32)
__device__ __half gEh[512 * 64];   // E hi, [n][k]
__device__ __half gEl[512 * 64];   // E lo, [n][k]

__device__ __forceinline__ uint32_t smem_u32(const void* p) {
    uint32_t a;
    asm("{ .reg .u64 t; cvta.to.shared.u64 t, %1; cvt.u32.u64 %0, t; }" : "=r"(a) : "l"(p));
    return a;
}
__device__ __forceinline__ uint32_t sw(uint32_t b) { return b ^ ((b >> 3) & 0x70); }

__device__ __forceinline__ void ldsm4(uint32_t r[4], uint32_t addr) {
    asm volatile("ldmatrix.sync.aligned.m8n8.x4.shared.b16 {%0,%1,%2,%3}, [%4];"
                 : "=r"(r[0]), "=r"(r[1]), "=r"(r[2]), "=r"(r[3]) : "r"(addr));
}
__device__ __forceinline__ void mma16816(float c[4], const uint32_t a[4],
                                         uint32_t b0, uint32_t b1) {
    asm volatile("mma.sync.aligned.m16n8k16.row.col.f32.f16.f16.f32 "
                 "{%0,%1,%2,%3}, {%4,%5,%6,%7}, {%8,%9}, {%0,%1,%2,%3};"
                 : "+f"(c[0]), "+f"(c[1]), "+f"(c[2]), "+f"(c[3])
                 : "r"(a[0]), "r"(a[1]), "r"(a[2]), "r"(a[3]), "r"(b0), "r"(b1));
}

__global__ void compute_h_kernel(const float* __restrict__ w) {
    int k = threadIdx.x;
    float s = 0.f;
    #pragma unroll
    for (int c = 0; c < 64; ++c) { float v = w[c * 512 + k]; s = fmaf(v, v, s); }
    g_h[k] = 0.5f * s;
}

__global__ void prep_e_kernel(const float* __restrict__ w) {
    int n = blockIdx.x * 256 + threadIdx.x;   // 0..511
    #pragma unroll
    for (int c = 0; c < 64; ++c) {
        float v = w[c * 512 + n];
        __half h = __float2half_rn(v);
        gEh[n * 64 + c] = h;
        gEl[n * 64 + c] = __float2half_rn(v - __half2float(h));
    }
}

__global__ __launch_bounds__(256, 2)
void vq_mma(const float* __restrict__ x, const float* __restrict__ w,
            float* __restrict__ out) {
    extern __shared__ char smem[];
    const uint32_t sb = smem_u32(smem);
    float* stage = (float*)smem;                 // [64][132] fp32, aliases E region
    float* hsm   = (float*)(smem + OFF_H);
    int*   bks   = (int*)(smem + OFF_BKS);

    const int tid = threadIdx.x;
    const int bg  = blockIdx.x >> 3;             // b*4+g
    const int mb  = blockIdx.x & 7;
    const int hw0 = mb * 128;

    // ---- stage x tile fp32 (coalesced) ----
    const float* xb = x + (size_t)bg * 65536 + hw0;
    {
        int m = tid & 127, ch = tid >> 7;
        #pragma unroll
        for (int c = ch; c < 64; c += 2) stage[c * 132 + m] = xb[c * 1024 + m];
    }
    hsm[tid]       = g_h[tid];
    hsm[tid + 256] = g_h[tid + 256];
    __syncthreads();

    // ---- split to fp16 hi/lo, swizzled [m][k] ----
    {
        int m = tid >> 1, c0 = (tid & 1) * 32;
        #pragma unroll
        for (int i = 0; i < 32; ++i) {
            int c = c0 + i;
            float v = stage[c * 132 + m];
            __half h = __float2half_rn(v);
            __half l = __float2half_rn(v - __half2float(h));
            uint32_t off = sw((uint32_t)(m * 128 + c * 2));
            *(__half*)(smem + OFF_XH + off) = h;
            *(__half*)(smem + OFF_XL + off) = l;
        }
    }
    __syncthreads();

    const int w8 = tid >> 5, lane = tid & 31;
    const int m0 = w8 * 16;
    const int group = lane >> 2, tig = lane & 3;

    // ---- load all A fragments once: 4 ksteps x (hi,lo) ----
    uint32_t ah[4][4], al[4][4];
    {
        uint32_t arow = (uint32_t)(m0 + (lane & 15));
        uint32_t acol = (uint32_t)((lane >> 4) * 16);
        #pragma unroll
        for (int ks = 0; ks < 4; ++ks) {
            uint32_t off = sw(arow * 128 + (uint32_t)ks * 32 + acol);
            ldsm4(ah[ks], sb + OFF_XH + off);
            ldsm4(al[ks], sb + OFF_XL + off);
        }
    }

    float best0v = -3.4e38f, best1v = -3.4e38f;
    int   best0k = 0,        best1k = 0;

    // B matrix row-addresses (non-trans; E is [n][k] so k is contiguous):
    // lanes 0-7: rows n0-7 @ k-bytes +0   (matrix0 -> b0 of c0)
    // lanes 8-15: rows n0-7 @ +16         (matrix1 -> b1 of c0)
    // lanes 16-23: rows n8-15 @ +0        (matrix2 -> b0 of c1)
    // lanes 24-31: rows n8-15 @ +16       (matrix3 -> b1 of c1)
    const uint32_t brow_l = (uint32_t)((lane & 7) + ((lane >> 4) & 1) * 8);
    const uint32_t bcol_l = (uint32_t)(((lane >> 3) & 1) * 16);

    for (int ch = 0; ch < 4; ++ch) {
        __syncthreads();   // stage/E readers done
        // ---- copy E chunk (128 codes) hi/lo into swizzled smem ----
        #pragma unroll
        for (int i = 0; i < 4; ++i) {
            int u = tid + i * 256;
            int r = u >> 3, seg = u & 7;
            uint32_t off = sw((uint32_t)(r * 128 + seg * 16));
            const char* srch = (const char*)(gEh + (ch * 128 + r) * 64) + seg * 16;
            const char* srcl = (const char*)(gEl + (ch * 128 + r) * 64) + seg * 16;
            *(uint4*)(smem + OFF_EH + off) = *(const uint4*)srch;
            *(uint4*)(smem + OFF_EL + off) = *(const uint4*)srcl;
        }
        __syncthreads();

        for (int jp = 0; jp < 8; ++jp) {       // pairs of 8-code n-tiles
            float c0[4] = {0, 0, 0, 0};
            float c1[4] = {0, 0, 0, 0};
            #pragma unroll
            for (int ks = 0; ks < 4; ++ks) {
                uint32_t boff = sw((uint32_t)(jp * 16) * 128 + brow_l * 128 +
                                   (uint32_t)ks * 32 + bcol_l);
                uint32_t bh[4], bl[4];
                ldsm4(bh, sb + OFF_EH + boff);
                ldsm4(bl, sb + OFF_EL + boff);
                // full 4-term split: (xh+xl).(eh+el), fp32 accumulate
                mma16816(c0, ah[ks], bh[0], bh[1]);
                mma16816(c0, al[ks], bh[0], bh[1]);
                mma16816(c0, ah[ks], bl[0], bl[1]);
                mma16816(c0, al[ks], bl[0], bl[1]);
                mma16816(c1, ah[ks], bh[2], bh[3]);
                mma16816(c1, al[ks], bh[2], bh[3]);
                mma16816(c1, ah[ks], bl[2], bl[3]);
                mma16816(c1, al[ks], bl[2], bl[3]);
            }
            // ---- fused argmax: ascending n per thread, strict > ----
            int nb = ch * 128 + jp * 16;
            float s;
            s = c0[0] - hsm[nb + 2 * tig];         if (s > best0v) { best0v = s; best0k = nb + 2 * tig; }
            s = c0[1] - hsm[nb + 2 * tig + 1];     if (s > best0v) { best0v = s; best0k = nb + 2 * tig + 1; }
            s = c1[0] - hsm[nb + 8 + 2 * tig];     if (s > best0v) { best0v = s; best0k = nb + 8 + 2 * tig; }
            s = c1[1] - hsm[nb + 8 + 2 * tig + 1]; if (s > best0v) { best0v = s; best0k = nb + 8 + 2 * tig + 1; }
            s = c0[2] - hsm[nb + 2 * tig];         if (s > best1v) { best1v = s; best1k = nb + 2 * tig; }
            s = c0[3] - hsm[nb + 2 * tig + 1];     if (s > best1v) { best1v = s; best1k = nb + 2 * tig + 1; }
            s = c1[2] - hsm[nb + 8 + 2 * tig];     if (s > best1v) { best1v = s; best1k = nb + 8 + 2 * tig; }
            s = c1[3] - hsm[nb + 8 + 2 * tig + 1]; if (s > best1v) { best1v = s; best1k = nb + 8 + 2 * tig + 1; }
        }
    }

    // ---- reduce across the 4 lanes sharing each row (tig dimension) ----
    #pragma unroll
    for (int off = 1; off <= 2; off <<= 1) {
        float ov; int ok;
        ov = __shfl_xor_sync(0xffffffffu, best0v, off);
        ok = __shfl_xor_sync(0xffffffffu, best0k, off);
        if (ov > best0v || (ov == best0v && ok < best0k)) { best0v = ov; best0k = ok; }
        ov = __shfl_xor_sync(0xffffffffu, best1v, off);
        ok = __shfl_xor_sync(0xffffffffu, best1k, off);
        if (ov > best1v || (ov == best1v && ok < best1k)) { best1v = ov; best1k = ok; }
    }
    if (tig == 0) {
        bks[m0 + group]     = best0k;
        bks[m0 + group + 8] = best1k;
    }
    __syncthreads();

    // ---- write argmins (as float) ----
    if (tid < 128)
        out[RESULT_ELEMS + bg * 1024 + hw0 + tid] = (float)bks[tid];

    // ---- write result: out[bg*64+c][hw0+m] = w[c][k]*0.5 (coalesced over m) ----
    {
        int m = tid & 127, ch = tid >> 7;
        int k = bks[m];
        float* ob = out + (size_t)bg * 65536 + hw0 + m;
        #pragma unroll
        for (int i = 0; i < 32; ++i) {
            int c = ch + i * 2;
            ob[(size_t)c * 1024] = w[c * 512 + k] * 0.5f;
        }
    }
}

extern "C" void kernel_launch(void* const* d_in, const int* in_sizes, int n_in,
                              void* d_out, int out_size) {
    const float* x = (const float*)d_in[0];   // (64,256,32,32) fp32
    const float* w = (const float*)d_in[1];   // (64,512) fp32
    float* out = (float*)d_out;               // result ++ argmins

    cudaFuncSetAttribute(vq_mma, cudaFuncAttributeMaxDynamicSharedMemorySize, SMEM_SZ);

    compute_h_kernel<<<1, 512>>>(w);
    prep_e_kernel<<<2, 256>>>(w);
    vq_mma<<<2048, 256, SMEM_SZ>>>(x, w, out);
}

// round 7
// speedup vs baseline: 1.9323x; 1.1113x over previous
#include <cuda_runtime.h>
#include <cuda_fp16.h>
#include <cstdint>

#define RESULT_ELEMS 16777216   // 64*256*32*32

// smem layout (bytes)
#define OFF_XH    0        // x hi [256][64] half swizzled, 32768
#define OFF_XL    32768    // x lo, 32768
#define OFF_EH    65536    // E chunk hi [128][64] half, 16384
#define OFF_EL    81920    // E chunk lo, 16384
#define OFF_H     98304    // 512 floats
#define OFF_BKS   100352   // 256 ints
#define SMEM_SZ   101376

__device__ float  g_h[512];        // 0.5*||e_k||^2 (exact fp32)
__device__ __half gEh[512 * 64];   // E hi, [n][k]
__device__ __half gEl[512 * 64];   // E lo, [n][k]

__device__ __forceinline__ uint32_t smem_u32(const void* p) {
    uint32_t a;
    asm("{ .reg .u64 t; cvta.to.shared.u64 t, %1; cvt.u32.u64 %0, t; }" : "=r"(a) : "l"(p));
    return a;
}
__device__ __forceinline__ uint32_t sw(uint32_t b) { return b ^ ((b >> 3) & 0x70); }

__device__ __forceinline__ void ldsm4(uint32_t r[4], uint32_t addr) {
    asm volatile("ldmatrix.sync.aligned.m8n8.x4.shared.b16 {%0,%1,%2,%3}, [%4];"
                 : "=r"(r[0]), "=r"(r[1]), "=r"(r[2]), "=r"(r[3]) : "r"(addr));
}
__device__ __forceinline__ void mma16816(float c[4], const uint32_t a[4],
                                         uint32_t b0, uint32_t b1) {
    asm volatile("mma.sync.aligned.m16n8k16.row.col.f32.f16.f16.f32 "
                 "{%0,%1,%2,%3}, {%4,%5,%6,%7}, {%8,%9}, {%0,%1,%2,%3};"
                 : "+f"(c[0]), "+f"(c[1]), "+f"(c[2]), "+f"(c[3])
                 : "r"(a[0]), "r"(a[1]), "r"(a[2]), "r"(a[3]), "r"(b0), "r"(b1));
}

__global__ void compute_h_kernel(const float* __restrict__ w) {
    int k = threadIdx.x;
    float s = 0.f;
    #pragma unroll
    for (int c = 0; c < 64; ++c) { float v = w[c * 512 + k]; s = fmaf(v, v, s); }
    g_h[k] = 0.5f * s;
}

__global__ void prep_e_kernel(const float* __restrict__ w) {
    int n = blockIdx.x * 256 + threadIdx.x;   // 0..511
    #pragma unroll
    for (int c = 0; c < 64; ++c) {
        float v = w[c * 512 + n];
        __half h = __float2half_rn(v);
        gEh[n * 64 + c] = h;
        gEl[n * 64 + c] = __float2half_rn(v - __half2float(h));
    }
}

__global__ __launch_bounds__(256, 2)
void vq_mma(const float* __restrict__ x, const float* __restrict__ w,
            float* __restrict__ out) {
    extern __shared__ char smem[];
    const uint32_t sb = smem_u32(smem);
    float* hsm = (float*)(smem + OFF_H);
    int*   bks = (int*)(smem + OFF_BKS);

    const int tid = threadIdx.x;
    const int bg  = blockIdx.x >> 2;             // b*4+g
    const int mt  = blockIdx.x & 3;
    const int hw0 = mt * 256;

    // ---- split x tile (256 rows) to fp16 hi/lo directly, swizzled [m][k] ----
    const float* xb = x + (size_t)bg * 65536 + hw0;
    {
        #pragma unroll
        for (int c2 = 0; c2 < 32; ++c2) {
            float v0 = xb[(size_t)(2 * c2) * 1024 + tid];
            float v1 = xb[(size_t)(2 * c2 + 1) * 1024 + tid];
            __half h0 = __float2half_rn(v0), h1 = __float2half_rn(v1);
            __half l0 = __float2half_rn(v0 - __half2float(h0));
            __half l1 = __float2half_rn(v1 - __half2float(h1));
            uint32_t off = sw((uint32_t)(tid * 128 + c2 * 4));
            *(__half2*)(smem + OFF_XH + off) = __halves2half2(h0, h1);
            *(__half2*)(smem + OFF_XL + off) = __halves2half2(l0, l1);
        }
    }
    hsm[tid]       = g_h[tid];
    hsm[tid + 256] = g_h[tid + 256];
    __syncthreads();

    const int w8 = tid >> 5, lane = tid & 31;
    const int m0 = w8 * 32;                      // 32 rows per warp (2 M-tiles)
    const int group = lane >> 2, tig = lane & 3;

    // ---- load all A fragments once: 2 M-tiles x 4 ksteps x (hi,lo) ----
    uint32_t ah[2][4][4], al[2][4][4];
    {
        uint32_t arow = (uint32_t)(lane & 15);
        uint32_t acol = (uint32_t)((lane >> 4) * 16);
        #pragma unroll
        for (int t = 0; t < 2; ++t)
            #pragma unroll
            for (int ks = 0; ks < 4; ++ks) {
                uint32_t off = sw((uint32_t)(m0 + t * 16 + arow) * 128 +
                                  (uint32_t)ks * 32 + acol);
                ldsm4(ah[t][ks], sb + OFF_XH + off);
                ldsm4(al[t][ks], sb + OFF_XL + off);
            }
    }

    float bestv[4];
    int   bestk[4];
    #pragma unroll
    for (int i = 0; i < 4; ++i) { bestv[i] = -3.4e38f; bestk[i] = 0; }

    // B row-addresses (E is [n][k], k contiguous; non-trans ldmatrix)
    const uint32_t brow_l = (uint32_t)((lane & 7) + ((lane >> 4) & 1) * 8);
    const uint32_t bcol_l = (uint32_t)(((lane >> 3) & 1) * 16);

    for (int ch = 0; ch < 4; ++ch) {
        __syncthreads();   // previous chunk's E readers done
        // ---- copy E chunk (128 codes) hi/lo into swizzled smem ----
        #pragma unroll
        for (int i = 0; i < 4; ++i) {
            int u = tid + i * 256;
            int r = u >> 3, seg = u & 7;
            uint32_t off = sw((uint32_t)(r * 128 + seg * 16));
            const char* srch = (const char*)(gEh + (ch * 128 + r) * 64) + seg * 16;
            const char* srcl = (const char*)(gEl + (ch * 128 + r) * 64) + seg * 16;
            *(uint4*)(smem + OFF_EH + off) = *(const uint4*)srch;
            *(uint4*)(smem + OFF_EL + off) = *(const uint4*)srcl;
        }
        __syncthreads();

        for (int jp = 0; jp < 8; ++jp) {       // pairs of 8-code n-tiles
            float cc[2][2][4];
            #pragma unroll
            for (int t = 0; t < 2; ++t)
                #pragma unroll
                for (int u = 0; u < 2; ++u)
                    #pragma unroll
                    for (int q = 0; q < 4; ++q) cc[t][u][q] = 0.f;

            #pragma unroll
            for (int ks = 0; ks < 4; ++ks) {
                uint32_t boff = sw((uint32_t)(jp * 16 + brow_l) * 128 +
                                   (uint32_t)ks * 32 + bcol_l);
                uint32_t bh[4], bl[4];
                ldsm4(bh, sb + OFF_EH + boff);
                ldsm4(bl, sb + OFF_EL + boff);
                #pragma unroll
                for (int t = 0; t < 2; ++t) {
                    // full 4-term split: (xh+xl).(eh+el), fp32 accumulate
                    mma16816(cc[t][0], ah[t][ks], bh[0], bh[1]);
                    mma16816(cc[t][0], al[t][ks], bh[0], bh[1]);
                    mma16816(cc[t][0], ah[t][ks], bl[0], bl[1]);
                    mma16816(cc[t][0], al[t][ks], bl[0], bl[1]);
                    mma16816(cc[t][1], ah[t][ks], bh[2], bh[3]);
                    mma16816(cc[t][1], al[t][ks], bh[2], bh[3]);
                    mma16816(cc[t][1], ah[t][ks], bl[2], bl[3]);
                    mma16816(cc[t][1], al[t][ks], bl[2], bl[3]);
                }
            }
            // ---- fused argmax: ascending n per thread, strict > ----
            int nb = ch * 128 + jp * 16;
            float h0 = hsm[nb + 2 * tig];
            float h1 = hsm[nb + 2 * tig + 1];
            float h2 = hsm[nb + 8 + 2 * tig];
            float h3 = hsm[nb + 8 + 2 * tig + 1];
            #pragma unroll
            for (int t = 0; t < 2; ++t) {
                float s;
                // row = m0 + t*16 + group  -> best index t*2
                s = cc[t][0][0] - h0; if (s > bestv[t*2]) { bestv[t*2] = s; bestk[t*2] = nb + 2*tig; }
                s = cc[t][0][1] - h1; if (s > bestv[t*2]) { bestv[t*2] = s; bestk[t*2] = nb + 2*tig + 1; }
                s = cc[t][1][0] - h2; if (s > bestv[t*2]) { bestv[t*2] = s; bestk[t*2] = nb + 8 + 2*tig; }
                s = cc[t][1][1] - h3; if (s > bestv[t*2]) { bestv[t*2] = s; bestk[t*2] = nb + 8 + 2*tig + 1; }
                // row = m0 + t*16 + group + 8 -> best index t*2+1
                s = cc[t][0][2] - h0; if (s > bestv[t*2+1]) { bestv[t*2+1] = s; bestk[t*2+1] = nb + 2*tig; }
                s = cc[t][0][3] - h1; if (s > bestv[t*2+1]) { bestv[t*2+1] = s; bestk[t*2+1] = nb + 2*tig + 1; }
                s = cc[t][1][2] - h2; if (s > bestv[t*2+1]) { bestv[t*2+1] = s; bestk[t*2+1] = nb + 8 + 2*tig; }
                s = cc[t][1][3] - h3; if (s > bestv[t*2+1]) { bestv[t*2+1] = s; bestk[t*2+1] = nb + 8 + 2*tig + 1; }
            }
        }
    }

    // ---- reduce across the 4 lanes sharing each row (tig dimension) ----
    #pragma unroll
    for (int i = 0; i < 4; ++i) {
        float v = bestv[i]; int k = bestk[i];
        #pragma unroll
        for (int off = 1; off <= 2; off <<= 1) {
            float ov = __shfl_xor_sync(0xffffffffu, v, off);
            int   ok = __shfl_xor_sync(0xffffffffu, k, off);
            if (ov > v || (ov == v && ok < k)) { v = ov; k = ok; }
        }
        if (tig == 0) bks[m0 + (i >> 1) * 16 + group + (i & 1) * 8] = k;
    }
    __syncthreads();

    // ---- write argmins (as float) ----
    out[RESULT_ELEMS + bg * 1024 + hw0 + tid] = (float)bks[tid];

    // ---- write result: out[bg*64+c][hw0+m] = w[c][k]*0.5 (coalesced over m) ----
    {
        int k = bks[tid];
        float* ob = out + (size_t)bg * 65536 + hw0 + tid;
        #pragma unroll 8
        for (int c = 0; c < 64; ++c)
            ob[(size_t)c * 1024] = w[c * 512 + k] * 0.5f;
    }
}

extern "C" void kernel_launch(void* const* d_in, const int* in_sizes, int n_in,
                              void* d_out, int out_size) {
    const float* x = (const float*)d_in[0];   // (64,256,32,32) fp32
    const float* w = (const float*)d_in[1];   // (64,512) fp32
    float* out = (float*)d_out;               // result ++ argmins

    cudaFuncSetAttribute(vq_mma, cudaFuncAttributeMaxDynamicSharedMemorySize, SMEM_SZ);

    compute_h_kernel<<<1, 512>>>(w);
    prep_e_kernel<<<2, 256>>>(w);
    vq_mma<<<1024, 256, SMEM_SZ>>>(x, w, out);
}